// round 14
// baseline (speedup 1.0000x reference)
#include <cuda_runtime.h>

// ---------------------------------------------------------------------------
// SlotAttention fused. B=32, N=16384, S=8, D=64, H=128, ITERS=3.
// k_pass: PERSISTENT grid (456 = 152 SMs x 3 CTAs); 2048 chunks of 256 rows;
//         per-warp cp.async ring-2 with paired phase-1 (wts broadcast shared
//         by both buffers), pipeline stays primed across chunk boundaries.
// k_update: 128 blocks x 256 threads; weights staged to smem; two (b,s)
//         pairs run concurrently in half-blocks.
// ---------------------------------------------------------------------------

#define BB 32
#define NN 16384
#define SS 8
#define DD 64
#define HH 128
#define CPB 64                   // chunks per batch (256 rows each)
#define NCHUNK (BB * CPB)        // 2048
#define GRID_PASS 456            // 152 SMs x 3 CTAs
#define PREC 528                 // floats per record: 512 Pacc + 8 Sg + 8 Sb
#define PASS_THREADS 128
// k_pass smem: xs 4096f4 + as4 512f4 + wts 128f4 + tail 80f = 76096 -> 76160
#define SMEM_BYTES 76160
#define ACTF 1344
#define UPD_SMEM ((13552 + 2 * (ACTF / 4)) * 16)   // 227584 bytes

typedef unsigned long long ull;

__device__ float  g_slots[BB * SS * DD];
__device__ float4 g_wts4[BB * 128];          // [b][k=0..15][s=0..7]
__device__ float  g_c0[BB][SS];
__device__ float  g_c1[BB][SS];
__device__ float4 g_part4[(size_t)NCHUNK * 132];

#define F2FMA(d, a, b) asm("fma.rn.f32x2 %0, %1, %2, %0;" : "+l"(d) : "l"(a), "l"(b))
#define F2ADD(d, a, b) asm("add.rn.f32x2 %0, %1, %2;" : "=l"(d) : "l"(a), "l"(b))
#define F2PACK(v, lo, hi) asm("mov.b64 %0, {%1, %2};" : "=l"(v) : "f"(lo), "f"(hi))
#define F2UNPK(lo, hi, v) asm("mov.b64 {%0, %1}, %2;" : "=f"(lo), "=f"(hi) : "l"(v))

#define CPA(dst, src) asm volatile("cp.async.cg.shared.global [%0], [%1], 16;" \
                                   :: "r"(dst), "l"(src))
#define CPCOMMIT() asm volatile("cp.async.commit_group;")
#define WAITG(n) asm volatile("cp.async.wait_group " #n ";" ::: "memory")

__device__ __forceinline__ float sigm(float x) { return 1.f / (1.f + __expf(-x)); }

__device__ __forceinline__ float dot16x4(const float4* a, const float4* w, float bias) {
    float a0 = 0.f, a1 = 0.f, a2 = 0.f, a3 = 0.f;
#pragma unroll
    for (int e = 0; e < 4; ++e) {
        float4 x0 = a[e],      w0 = w[e];
        float4 x1 = a[e + 4],  w1 = w[e + 4];
        float4 x2 = a[e + 8],  w2 = w[e + 8];
        float4 x3 = a[e + 12], w3 = w[e + 12];
        a0 = fmaf(x0.x, w0.x, fmaf(x0.y, w0.y, fmaf(x0.z, w0.z, fmaf(x0.w, w0.w, a0))));
        a1 = fmaf(x1.x, w1.x, fmaf(x1.y, w1.y, fmaf(x1.z, w1.z, fmaf(x1.w, w1.w, a1))));
        a2 = fmaf(x2.x, w2.x, fmaf(x2.y, w2.y, fmaf(x2.z, w2.z, fmaf(x2.w, w2.w, a2))));
        a3 = fmaf(x3.x, w3.x, fmaf(x3.y, w3.y, fmaf(x3.z, w3.z, fmaf(x3.w, w3.w, a3))));
    }
    return bias + ((a0 + a1) + (a2 + a3));
}
__device__ __forceinline__ float dot8x4(const float4* a, const float4* w) {
    float a0 = 0.f, a1 = 0.f;
#pragma unroll
    for (int e = 0; e < 4; ++e) {
        float4 x0 = a[e],     w0 = w[e];
        float4 x1 = a[e + 4], w1 = w[e + 4];
        a0 = fmaf(x0.x, w0.x, fmaf(x0.y, w0.y, fmaf(x0.z, w0.z, fmaf(x0.w, w0.w, a0))));
        a1 = fmaf(x1.x, w1.x, fmaf(x1.y, w1.y, fmaf(x1.z, w1.z, fmaf(x1.w, w1.w, a1))));
    }
    return a0 + a1;
}

__device__ __forceinline__ void ln64_warp(const float* in, float* out,
                                          const float* g,
                                          const float* bt, int t) {
    if (t < 32) {
        float v0 = in[t], v1 = in[t + 32];
        float sum = v0 + v1;
        float sq  = fmaf(v0, v0, v1 * v1);
#pragma unroll
        for (int off = 16; off; off >>= 1) {
            sum += __shfl_xor_sync(0xffffffffu, sum, off);
            sq  += __shfl_xor_sync(0xffffffffu, sq,  off);
        }
        float m    = sum * (1.f / 64.f);
        float istd = rsqrtf(fmaf(sq, 1.f / 64.f, -m * m) + 1e-5f);
        out[t]      = fmaf((v0 - m) * istd, g[t],      bt[t]);
        out[t + 32] = fmaf((v1 - m) * istd, g[t + 32], bt[t + 32]);
    }
}

// ---------------------------------------------------------------------------
__device__ __forceinline__ void prep_slot(
    int b, int s, int t,
    const float* snew, float* lns, float* qv, float* qtv, float* hpart,
    const float* lnsg, const float* lnsb,
    const float* Wq,   const float* Wk,
    const float* lng,  const float* lnb)
{
    ln64_warp(snew, lns, lnsg, lnsb, t);
    __syncthreads();
    {
        int dd = t & 63, h = t >> 6;
        const float4* wr = (const float4*)(Wq + dd * 64) + h * 8;
        const float4* lv = (const float4*)lns + h * 8;
        hpart[t] = dot8x4(lv, wr);
    }
    __syncthreads();
    if (t < 64) qv[t] = (hpart[t] + hpart[t + 64]) * 0.125f;
    __syncthreads();
    {
        int e = t & 63, h = t >> 6;
        float acc = 0.f;
        const float* wk = Wk + (h * 32) * 64 + e;
#pragma unroll 8
        for (int dd = 0; dd < 32; ++dd) acc = fmaf(qv[h * 32 + dd], wk[dd * 64], acc);
        hpart[t] = acc;
    }
    __syncthreads();
    if (t < 64) qtv[t] = hpart[t] + hpart[t + 64];
    __syncthreads();
    if (t < 64) {
        int k = t >> 2, j = t & 3;
        reinterpret_cast<float*>(g_wts4 + b * 128)[(k * 8 + s) * 4 + j] = lng[t] * qtv[t];
    }
    if (t < 32) {
        float p1 = fmaf(lng[t + 32], qtv[t + 32], lng[t] * qtv[t]);
        float p0 = fmaf(lnb[t + 32], qtv[t + 32], lnb[t] * qtv[t]);
#pragma unroll
        for (int off = 16; off; off >>= 1) {
            p1 += __shfl_xor_sync(0xffffffffu, p1, off);
            p0 += __shfl_xor_sync(0xffffffffu, p0, off);
        }
        if (t == 0) { g_c1[b][s] = p1; g_c0[b][s] = p0; }
    }
}

// ---------------------------------------------------------------------------
__global__ void __launch_bounds__(128) k_init(
    const float* __restrict__ noise, const float* __restrict__ mu,
    const float* __restrict__ lsig,
    const float* __restrict__ lnsg, const float* __restrict__ lnsb,
    const float* __restrict__ Wq,   const float* __restrict__ Wk,
    const float* __restrict__ lng,  const float* __restrict__ lnb)
{
    __shared__ __align__(16) float snew[64], lns[64], qv[64], qtv[64], hpart[128];
    int bs = blockIdx.x, b = bs >> 3, s = bs & 7, t = threadIdx.x;
    if (t < 64) {
        int idx = s * 64 + t;
        float v = fmaf(__expf(lsig[idx]), noise[b * 512 + idx], mu[idx]);
        snew[t] = v;
        g_slots[b * 512 + idx] = v;
    }
    __syncthreads();
    prep_slot(b, s, t, snew, lns, qv, qtv, hpart, lnsg, lnsb, Wq, Wk, lng, lnb);
}

// ---------------------------------------------------------------------------
__device__ __forceinline__ void stage_tile(const float4* __restrict__ gsrc,
                                           unsigned sdst, int l)
{
#pragma unroll
    for (int j = 0; j < 16; ++j) {
        int flat = j * 32 + l;
        int row = flat >> 4, k = flat & 15;
        unsigned dst = sdst + (unsigned)((row * 16 + (k ^ (row & 15))) * 16);
        CPA(dst, gsrc + flat);
    }
    CPCOMMIT();
}

__device__ __forceinline__ void p1_epilogue(
    const ull* d2, ull sum2, ull sqa, ull sqb,
    const float* c0r, const float* c1r,
    float* gacc, float* bacc, float4* dst, int l)
{
    float slo, shi; F2UNPK(slo, shi, sum2);
    float sum = slo + shi;
    float qa0, qa1, qb0, qb1;
    F2UNPK(qa0, qa1, sqa); F2UNPK(qb0, qb1, sqb);
    float sq = (qa0 + qa1) + (qb0 + qb1);
    float m    = sum * (1.f / 64.f);
    float istd = rsqrtf(fmaf(sq, 1.f / 64.f, -m * m) + 1e-5f);
    float lo[8], mx = -3.4e38f;
#pragma unroll
    for (int s = 0; s < 8; ++s) {
        float dlo, dhi; F2UNPK(dlo, dhi, d2[s]);
        float d = dlo + dhi;
        lo[s] = fmaf(istd, fmaf(-m, c1r[s], d), c0r[s]);
        mx = fmaxf(mx, lo[s]);
    }
    float pr[8], ps = 0.f;
#pragma unroll
    for (int s = 0; s < 8; ++s) { pr[s] = __expf(lo[s] - mx); ps += pr[s]; }
    float rc  = 1.f / ps;
    float tmi = m * istd;
    float al[8];
#pragma unroll
    for (int s = 0; s < 8; ++s) {
        float a = fmaf(pr[s], rc, 1e-8f);   // softmax + EPS
        gacc[s] += a;
        bacc[s] = fmaf(a, tmi, bacc[s]);
        al[s]   = a * istd;
    }
    dst[l * 2 + 0] = make_float4(al[0], al[1], al[2], al[3]);
    dst[l * 2 + 1] = make_float4(al[4], al[5], al[6], al[7]);
}

__device__ __forceinline__ void p2_accum(
    const ulonglong2* xs2w, const float4* as4t, ull* p2, int g2, int e4)
{
#pragma unroll 4
    for (int r = 0; r < 32; ++r) {
        float4 av = as4t[r * 2 + g2];
        ulonglong2 xq = xs2w[r * 16 + (e4 ^ (r & 15))];
        ull a0, a1, a2, a3;
        F2PACK(a0, av.x, av.x); F2PACK(a1, av.y, av.y);
        F2PACK(a2, av.z, av.z); F2PACK(a3, av.w, av.w);
        F2FMA(p2[0], xq.x, a0); F2FMA(p2[1], xq.y, a0);
        F2FMA(p2[2], xq.x, a1); F2FMA(p2[3], xq.y, a1);
        F2FMA(p2[4], xq.x, a2); F2FMA(p2[5], xq.y, a2);
        F2FMA(p2[6], xq.x, a3); F2FMA(p2[7], xq.y, a3);
    }
}

// ---------------------------------------------------------------------------
// persistent paired-pipeline pass. Each block walks chunks bid, bid+456, ...
// chunk c: batch b = c>>6, 256 rows at (c&63)*256. Warp w owns 64 rows
// (two 32-row tiles). Pipeline stays primed across chunks.
// ---------------------------------------------------------------------------
__global__ void __launch_bounds__(PASS_THREADS, 3) k_pass(const float4* __restrict__ x4)
{
    extern __shared__ __align__(16) float4 smem[];
    float4* xs   = smem;
    float4* as4  = smem + 4096;          // alphas; reused as reduce scratch
    float4* wts  = smem + 4608;
    float*  tail = (float*)(smem + 4736);   // 80 floats

    const int t = threadIdx.x;
    const int w = t >> 5, l = t & 31;
    const int g2 = l >> 4, e4 = l & 15;

    unsigned smem_u32;
    { size_t a = __cvta_generic_to_shared(xs); smem_u32 = (unsigned)a; }
    const unsigned xs_base = smem_u32 + (unsigned)(w * 1024 * 16);

    int c = blockIdx.x;
    const float4* gw = x4 + ((size_t)(c >> 6) * NN + (size_t)(c & 63) * 256 + w * 64) * 16;
    stage_tile(gw,       xs_base,        l);   // tile A
    stage_tile(gw + 512, xs_base + 8192, l);   // tile B

    wts[t] = g_wts4[(c >> 6) * 128 + t];
    if (t < 8)  tail[t] = g_c0[c >> 6][t];
    if (t >= 8 && t < 16) tail[t] = g_c1[c >> 6][t - 8];
    __syncthreads();

    const ulonglong2* wt2 = reinterpret_cast<const ulonglong2*>(wts);
    float4* as4w = as4 + w * 128;
    const ulonglong2* xsA = reinterpret_cast<const ulonglong2*>(xs + w * 1024);
    const ulonglong2* xsB = reinterpret_cast<const ulonglong2*>(xs + w * 1024 + 512);

    float c0r[8], c1r[8], gacc[8], bacc[8];
    ull p2[8];
#pragma unroll
    for (int s = 0; s < 8; ++s) {
        c0r[s] = tail[s]; c1r[s] = tail[8 + s];
        gacc[s] = 0.f; bacc[s] = 0.f; p2[s] = 0ULL;
    }

    for (;;) {
        const int cn = c + GRID_PASS;
        const bool have_next = (cn < NCHUNK);
        const float4* gwn = have_next
            ? x4 + ((size_t)(cn >> 6) * NN + (size_t)(cn & 63) * 256 + w * 64) * 16
            : gw;

        WAITG(0);
        __syncwarp();

        // ---- paired phase 1 ----
        {
            ull dA[8], dB[8];
#pragma unroll
            for (int s = 0; s < 8; ++s) { dA[s] = 0ULL; dB[s] = 0ULL; }
            ull sumA = 0ULL, sumB = 0ULL, sqaA = 0ULL, sqaB = 0ULL, sqbA = 0ULL, sqbB = 0ULL;
            const int rb = l * 16, ro = l & 15;
#pragma unroll
            for (int k = 0; k < 16; ++k) {
                ulonglong2 vA = xsA[rb + (k ^ ro)];
                ulonglong2 vB = xsB[rb + (k ^ ro)];
                ull tv;
                F2ADD(tv, vA.x, vA.y); F2ADD(sumA, sumA, tv);
                F2ADD(tv, vB.x, vB.y); F2ADD(sumB, sumB, tv);
                F2FMA(sqaA, vA.x, vA.x); F2FMA(sqbA, vA.y, vA.y);
                F2FMA(sqaB, vB.x, vB.x); F2FMA(sqbB, vB.y, vB.y);
#pragma unroll
                for (int s = 0; s < 8; ++s) {
                    ulonglong2 wv = wt2[k * 8 + s];
                    F2FMA(dA[s], vA.x, wv.x); F2FMA(dA[s], vA.y, wv.y);
                    F2FMA(dB[s], vB.x, wv.x); F2FMA(dB[s], vB.y, wv.y);
                }
            }
            p1_epilogue(dA, sumA, sqaA, sqbA, c0r, c1r, gacc, bacc, as4w,      l);
            p1_epilogue(dB, sumB, sqaB, sqbB, c0r, c1r, gacc, bacc, as4w + 64, l);
        }
        __syncwarp();

        // ---- phase 2 + stage next chunk's tiles into same buffers ----
        p2_accum(xsA, as4w, p2, g2, e4);
        if (have_next) stage_tile(gwn,       xs_base,        l);
        p2_accum(xsB, as4w + 64, p2, g2, e4);
        if (have_next) stage_tile(gwn + 512, xs_base + 8192, l);
        __syncwarp();

        // ---- per-chunk flush: Sg/Sb + cross-warp Pacc reduce -> g_part ----
#pragma unroll
        for (int s = 0; s < 8; ++s) {
            float gv = gacc[s], bv = bacc[s];
#pragma unroll
            for (int off = 16; off; off >>= 1) {
                gv += __shfl_xor_sync(0xffffffffu, gv, off);
                bv += __shfl_xor_sync(0xffffffffu, bv, off);
            }
            if (l == 0) { tail[16 + w * 8 + s] = gv; tail[48 + w * 8 + s] = bv; }
        }
        // write own warp's partials into as4 scratch (alphas now dead)
#pragma unroll
        for (int ss = 0; ss < 4; ++ss) {
            float x0, x1, x2, x3;
            F2UNPK(x0, x1, p2[2 * ss]);
            F2UNPK(x2, x3, p2[2 * ss + 1]);
            as4[w * 128 + (4 * g2 + ss) * 16 + e4] = make_float4(x0, x1, x2, x3);
        }
        __syncthreads();

        {
            float4* gp4 = g_part4 + (size_t)c * 132;
            float4 a = as4[t], bb2 = as4[128 + t], cc = as4[256 + t], d = as4[384 + t];
            float4 o;
            o.x = ((a.x + bb2.x) + cc.x) + d.x;
            o.y = ((a.y + bb2.y) + cc.y) + d.y;
            o.z = ((a.z + bb2.z) + cc.z) + d.z;
            o.w = ((a.w + bb2.w) + cc.w) + d.w;
            gp4[t] = o;
            if (t < 16) {
                const float* src = tail + 16 + (t >= 8 ? 32 : 0) + (t & 7);
                float v = ((src[0] + src[8]) + src[16]) + src[24];
                reinterpret_cast<float*>(gp4)[512 + (t >= 8 ? 8 : 0) + (t & 7)] = v;
            }
        }
        if (!have_next) break;

        // ---- advance to next chunk: reload wts/c0/c1 if batch changed ----
        __syncthreads();            // as4/tail reads done
        wts[t] = g_wts4[(cn >> 6) * 128 + t];
        if (t < 8)  tail[t] = g_c0[cn >> 6][t];
        if (t >= 8 && t < 16) tail[t] = g_c1[cn >> 6][t - 8];
        __syncthreads();
#pragma unroll
        for (int s = 0; s < 8; ++s) {
            c0r[s] = tail[s]; c1r[s] = tail[8 + s];
            gacc[s] = 0.f; bacc[s] = 0.f; p2[s] = 0ULL;
        }
        c = cn;
        gw = gwn;
    }
}

// ---------------------------------------------------------------------------
// slot update: 128 blocks x 256 threads; half-block hb handles (b0+16*hb, s).
// ---------------------------------------------------------------------------
__global__ void __launch_bounds__(256) k_update(
    const float* __restrict__ lng,  const float* __restrict__ lnb,
    const float* __restrict__ lnsg, const float* __restrict__ lnsb,
    const float* __restrict__ lnmg, const float* __restrict__ lnmb,
    const float* __restrict__ Wq,   const float* __restrict__ Wk,
    const float* __restrict__ Wv,
    const float* __restrict__ W_ih, const float* __restrict__ W_hh,
    const float* __restrict__ b_ih, const float* __restrict__ b_hh,
    const float* __restrict__ W1,   const float* __restrict__ b1,
    const float* __restrict__ W2,   const float* __restrict__ b2,
    float* __restrict__ out, int last)
{
    extern __shared__ __align__(16) float4 smu[];
    float4* sWv  = smu;
    float4* sWih = smu + 1024;
    float4* sWhh = smu + 4096;
    float4* sW1  = smu + 7168;
    float4* sW2  = smu + 9216;
    float4* sWq  = smu + 11264;
    float4* sWk  = smu + 12288;
    float*  sPar = (float*)(smu + 13312);

    float *sBih = sPar, *sBhh = sPar + 192, *sB1 = sPar + 384, *sB2 = sPar + 512;
    float *sLng = sPar + 576, *sLnb = sPar + 640, *sLnsg = sPar + 704;
    float *sLnsb = sPar + 768, *sLnmg = sPar + 832, *sLnmb = sPar + 896;

    const int bx = blockIdx.x, b0 = bx >> 3, s = bx & 7;
    const int t = threadIdx.x;
    const int hb = t >> 7, t2 = t & 127;
    const int b = b0 + 16 * hb;

    float* act = (float*)(smu + 13552) + hb * ACTF;
    float *P = act, *Uv = act + 64, *upds = act + 128, *slp = act + 192;
    float *updh = act + 256, *mln = act + 320, *snew = act + 384;
    float *lns = act + 448, *qv = act + 512, *qtv = act + 576;
    float *gi = act + 640, *gh = act + 832, *hhs = act + 1024, *hpart = act + 1152;
    float4* pg4 = (float4*)(act + 640);   // aliases gi (consumed before D)
    float*  sred = act + 1280;
    float*  sS   = act + 1288;

    unsigned sb;
    { size_t a = __cvta_generic_to_shared(smu); sb = (unsigned)a; }
    const unsigned parU = sb + 13312u * 16u;

    for (int i = t; i < 1024; i += 256) CPA(sb + i * 16, (const float4*)Wv + i);
    if (t < 48) CPA(parU + t * 16,          (const float4*)b_ih + t);
    if (t >= 48 && t < 96)  CPA(parU + t * 16, (const float4*)b_hh + (t - 48));
    if (t >= 96 && t < 128) CPA(parU + t * 16, (const float4*)b1 + (t - 96));
    if (t >= 128 && t < 144) CPA(parU + t * 16, (const float4*)b2 + (t - 128));
    if (t >= 144 && t < 160) CPA(parU + t * 16, (const float4*)lng + (t - 144));
    if (t >= 160 && t < 176) CPA(parU + t * 16, (const float4*)lnb + (t - 160));
    if (t >= 176 && t < 192) CPA(parU + t * 16, (const float4*)lnsg + (t - 176));
    if (t >= 192 && t < 208) CPA(parU + t * 16, (const float4*)lnsb + (t - 192));
    if (t >= 208 && t < 224) CPA(parU + t * 16, (const float4*)lnmg + (t - 208));
    if (t >= 224 && t < 240) CPA(parU + t * 16, (const float4*)lnmb + (t - 224));
    CPCOMMIT();
    for (int i = t; i < 3072; i += 256) CPA(sb + (1024 + i) * 16, (const float4*)W_ih + i);
    CPCOMMIT();
    for (int i = t; i < 3072; i += 256) CPA(sb + (4096 + i) * 16, (const float4*)W_hh + i);
    CPCOMMIT();

    // ---- A: reduce 64 records (4 groups x 16, fixed order) ----
    {
        const float4* pb4 = g_part4 + (size_t)b * CPB * 132;
        if (t2 < 64) {
            int e4 = t2 & 15, grp = t2 >> 4;
            const float4* src = pb4 + (size_t)grp * 16 * 132 + s * 16 + e4;
            float4 acc = make_float4(0.f, 0.f, 0.f, 0.f);
#pragma unroll
            for (int j = 0; j < 16; ++j) {
                float4 v = src[(size_t)j * 132];
                acc.x += v.x; acc.y += v.y; acc.z += v.z; acc.w += v.w;
            }
            pg4[grp * 16 + e4] = acc;
        } else if (t2 < 72) {
            int which = (t2 - 64) >> 2;
            int grp = (t2 - 64) & 3;
            const float* src = reinterpret_cast<const float*>(pb4)
                             + (size_t)grp * 16 * PREC + 512 + which * 8 + s;
            float acc = 0.f;
#pragma unroll
            for (int j = 0; j < 16; ++j) acc += src[(size_t)j * PREC];
            sred[t2 - 64] = acc;
        }
        if (t2 >= 64) slp[t2 - 64] = g_slots[b * 512 + s * 64 + (t2 - 64)];
    }

    for (int i = t; i < 2048; i += 256) CPA(sb + (7168 + i) * 16, (const float4*)W1 + i);
    CPCOMMIT();
    for (int i = t; i < 2048; i += 256) CPA(sb + (9216 + i) * 16, (const float4*)W2 + i);
    CPCOMMIT();
    for (int i = t; i < 1024; i += 256) CPA(sb + (11264 + i) * 16, (const float4*)Wq + i);
    CPCOMMIT();
    for (int i = t; i < 1024; i += 256) CPA(sb + (12288 + i) * 16, (const float4*)Wk + i);
    CPCOMMIT();

    WAITG(6);
    __syncthreads();
    if (t2 < 16) {
        float4 a = pg4[t2], bg = pg4[16 + t2], c = pg4[32 + t2], d = pg4[48 + t2];
        float4 o;
        o.x = ((a.x + bg.x) + c.x) + d.x;
        o.y = ((a.y + bg.y) + c.y) + d.y;
        o.z = ((a.z + bg.z) + c.z) + d.z;
        o.w = ((a.w + bg.w) + c.w) + d.w;
        reinterpret_cast<float4*>(P)[t2] = o;
    }
    if (t2 == 0) sS[0] = ((sred[0] + sred[1]) + sred[2]) + sred[3];
    if (t2 == 1) sS[1] = ((sred[4] + sred[5]) + sred[6]) + sred[7];
    __syncthreads();

    if (t2 < 64) Uv[t2] = fmaf(sLng[t2], P[t2] - sS[1], sLnb[t2] * sS[0]) / sS[0];
    __syncthreads();

    {
        int dd = t2 & 63, h = t2 >> 6;
        float r = dot8x4((const float4*)Uv + h * 8, sWv + dd * 16 + h * 8);
        __syncthreads();
        hpart[t2] = r;
    }
    __syncthreads();
    if (t2 < 64) upds[t2] = hpart[t2] + hpart[t2 + 64];
    WAITG(4);
    __syncthreads();

#pragma unroll
    for (int k = 0; k < 3; ++k) {
        int id = t2 + 128 * k;
        if (id < 192) {
            gi[id] = dot16x4((const float4*)upds, sWih + id * 16, sBih[id]);
        } else {
            int j = id - 192;
            gh[j] = dot16x4((const float4*)slp, sWhh + j * 16, sBhh[j]);
        }
    }
    __syncthreads();

    if (t2 < 64) {
        float r = sigm(gi[t2]      + gh[t2]);
        float z = sigm(gi[64 + t2] + gh[64 + t2]);
        float n = tanhf(fmaf(r, gh[128 + t2], gi[128 + t2]));
        updh[t2] = fmaf(z, slp[t2] - n, n);
    }
    __syncthreads();

    ln64_warp(updh, mln, sLnmg, sLnmb, t2);
    WAITG(3);
    __syncthreads();

    hhs[t2] = fmaxf(dot16x4((const float4*)mln, sW1 + t2 * 16, sB1[t2]), 0.f);
    WAITG(2);
    __syncthreads();

    {
        int dd = t2 & 63, h = t2 >> 6;
        float r = dot16x4((const float4*)hhs + h * 16, sW2 + dd * 32 + h * 16, 0.f);
        __syncthreads();
        hpart[t2] = r;
    }
    __syncthreads();
    if (t2 < 64) {
        float v = updh[t2] + sB2[t2] + (hpart[t2] + hpart[t2 + 64]);
        snew[t2] = v;
        g_slots[b * 512 + s * 64 + t2] = v;
        if (last) out[b * 512 + s * 64 + t2] = v;
    }
    WAITG(0);
    __syncthreads();

    if (!last)
        prep_slot(b, s, t2, snew, lns, qv, qtv, hpart, sLnsg, sLnsb,
                  (const float*)sWq, (const float*)sWk, sLng, sLnb);
}

// ---------------------------------------------------------------------------
extern "C" void kernel_launch(void* const* d_in, const int* in_sizes, int n_in,
                              void* d_out, int out_size)
{
    const float* x     = (const float*)d_in[0];
    const float* noise = (const float*)d_in[1];
    const float* mu    = (const float*)d_in[2];
    const float* lsig  = (const float*)d_in[3];
    const float* lng   = (const float*)d_in[4];
    const float* lnb   = (const float*)d_in[5];
    const float* lnsg  = (const float*)d_in[6];
    const float* lnsb  = (const float*)d_in[7];
    const float* lnmg  = (const float*)d_in[8];
    const float* lnmb  = (const float*)d_in[9];
    const float* Wq    = (const float*)d_in[10];
    const float* Wk    = (const float*)d_in[11];
    const float* Wv    = (const float*)d_in[12];
    const float* W_ih  = (const float*)d_in[13];
    const float* W_hh  = (const float*)d_in[14];
    const float* b_ih  = (const float*)d_in[15];
    const float* b_hh  = (const float*)d_in[16];
    const float* W1    = (const float*)d_in[17];
    const float* b1    = (const float*)d_in[18];
    const float* W2    = (const float*)d_in[19];
    const float* b2    = (const float*)d_in[20];
    float* out = (float*)d_out;

    cudaFuncSetAttribute(k_pass, cudaFuncAttributeMaxDynamicSharedMemorySize, SMEM_BYTES);
    cudaFuncSetAttribute(k_update, cudaFuncAttributeMaxDynamicSharedMemorySize, UPD_SMEM);

    k_init<<<BB * SS, 128>>>(noise, mu, lsig, lnsg, lnsb, Wq, Wk, lng, lnb);

    for (int it = 0; it < 3; ++it) {
        k_pass<<<GRID_PASS, PASS_THREADS, SMEM_BYTES>>>((const float4*)x);
        k_update<<<128, 256, UPD_SMEM>>>(lng, lnb, lnsg, lnsb, lnmg, lnmb,
                                         Wq, Wk, Wv, W_ih, W_hh, b_ih, b_hh,
                                         W1, b1, W2, b2, out, it == 2);
    }
}

// round 15
// speedup vs baseline: 1.0760x; 1.0760x over previous
#include <cuda_runtime.h>

// ---------------------------------------------------------------------------
// SlotAttention fused. B=32, N=16384, S=8, D=64, H=128, ITERS=3.
// k_pass: per-warp cp.async ring-2, paired phase-1 (round-12/13 winner).
// k_update: 128 blocks x 256 threads, weights staged to smem, two (b,s)
//           pairs concurrent in half-blocks.
// NEW: Programmatic Dependent Launch — each kernel stages its independent
//      inputs (x tiles / weight matrices) BEFORE griddepcontrol.wait, hiding
//      staging and launch latency under the predecessor's tail wave.
// ---------------------------------------------------------------------------

#define BB 32
#define NN 16384
#define SS 8
#define DD 64
#define HH 128
#define NBLKX 32                 // pass blocks per batch (512 rows each)
#define PREC 528                 // floats per record: 512 Pacc + 8 Sg + 8 Sb
#define PASS_THREADS 128
// k_pass smem: xs 4096f4 + as4 512f4 + wts 128f4 + tail 80f = 76096 -> 76160
#define SMEM_BYTES 76160
#define ACTF 1344
#define UPD_SMEM ((13552 + 2 * (ACTF / 4)) * 16)   // 227584 bytes

typedef unsigned long long ull;

__device__ float  g_slots[BB * SS * DD];
__device__ float4 g_wts4[BB * 128];          // [b][k=0..15][s=0..7]
__device__ float  g_c0[BB][SS];
__device__ float  g_c1[BB][SS];
__device__ float4 g_part4[(size_t)BB * NBLKX * 132];

#define F2FMA(d, a, b) asm("fma.rn.f32x2 %0, %1, %2, %0;" : "+l"(d) : "l"(a), "l"(b))
#define F2ADD(d, a, b) asm("add.rn.f32x2 %0, %1, %2;" : "=l"(d) : "l"(a), "l"(b))
#define F2PACK(v, lo, hi) asm("mov.b64 %0, {%1, %2};" : "=l"(v) : "f"(lo), "f"(hi))
#define F2UNPK(lo, hi, v) asm("mov.b64 {%0, %1}, %2;" : "=f"(lo), "=f"(hi) : "l"(v))

#define CPA(dst, src) asm volatile("cp.async.cg.shared.global [%0], [%1], 16;" \
                                   :: "r"(dst), "l"(src))
#define CPCOMMIT() asm volatile("cp.async.commit_group;")
#define WAITG(n) asm volatile("cp.async.wait_group " #n ";" ::: "memory")
#define GRID_WAIT() asm volatile("griddepcontrol.wait;" ::: "memory")
#define GRID_LAUNCH_DEP() asm volatile("griddepcontrol.launch_dependents;" ::: "memory")

__device__ __forceinline__ float sigm(float x) { return 1.f / (1.f + __expf(-x)); }

__device__ __forceinline__ float dot16x4(const float4* a, const float4* w, float bias) {
    float a0 = 0.f, a1 = 0.f, a2 = 0.f, a3 = 0.f;
#pragma unroll
    for (int e = 0; e < 4; ++e) {
        float4 x0 = a[e],      w0 = w[e];
        float4 x1 = a[e + 4],  w1 = w[e + 4];
        float4 x2 = a[e + 8],  w2 = w[e + 8];
        float4 x3 = a[e + 12], w3 = w[e + 12];
        a0 = fmaf(x0.x, w0.x, fmaf(x0.y, w0.y, fmaf(x0.z, w0.z, fmaf(x0.w, w0.w, a0))));
        a1 = fmaf(x1.x, w1.x, fmaf(x1.y, w1.y, fmaf(x1.z, w1.z, fmaf(x1.w, w1.w, a1))));
        a2 = fmaf(x2.x, w2.x, fmaf(x2.y, w2.y, fmaf(x2.z, w2.z, fmaf(x2.w, w2.w, a2))));
        a3 = fmaf(x3.x, w3.x, fmaf(x3.y, w3.y, fmaf(x3.z, w3.z, fmaf(x3.w, w3.w, a3))));
    }
    return bias + ((a0 + a1) + (a2 + a3));
}
__device__ __forceinline__ float dot8x4(const float4* a, const float4* w) {
    float a0 = 0.f, a1 = 0.f;
#pragma unroll
    for (int e = 0; e < 4; ++e) {
        float4 x0 = a[e],     w0 = w[e];
        float4 x1 = a[e + 4], w1 = w[e + 4];
        a0 = fmaf(x0.x, w0.x, fmaf(x0.y, w0.y, fmaf(x0.z, w0.z, fmaf(x0.w, w0.w, a0))));
        a1 = fmaf(x1.x, w1.x, fmaf(x1.y, w1.y, fmaf(x1.z, w1.z, fmaf(x1.w, w1.w, a1))));
    }
    return a0 + a1;
}

__device__ __forceinline__ void ln64_warp(const float* in, float* out,
                                          const float* g,
                                          const float* bt, int t) {
    if (t < 32) {
        float v0 = in[t], v1 = in[t + 32];
        float sum = v0 + v1;
        float sq  = fmaf(v0, v0, v1 * v1);
#pragma unroll
        for (int off = 16; off; off >>= 1) {
            sum += __shfl_xor_sync(0xffffffffu, sum, off);
            sq  += __shfl_xor_sync(0xffffffffu, sq,  off);
        }
        float m    = sum * (1.f / 64.f);
        float istd = rsqrtf(fmaf(sq, 1.f / 64.f, -m * m) + 1e-5f);
        out[t]      = fmaf((v0 - m) * istd, g[t],      bt[t]);
        out[t + 32] = fmaf((v1 - m) * istd, g[t + 32], bt[t + 32]);
    }
}

// ---------------------------------------------------------------------------
__device__ __forceinline__ void prep_slot(
    int b, int s, int t,
    const float* snew, float* lns, float* qv, float* qtv, float* hpart,
    const float* lnsg, const float* lnsb,
    const float* Wq,   const float* Wk,
    const float* lng,  const float* lnb)
{
    ln64_warp(snew, lns, lnsg, lnsb, t);
    __syncthreads();
    {
        int dd = t & 63, h = t >> 6;
        const float4* wr = (const float4*)(Wq + dd * 64) + h * 8;
        const float4* lv = (const float4*)lns + h * 8;
        hpart[t] = dot8x4(lv, wr);
    }
    __syncthreads();
    if (t < 64) qv[t] = (hpart[t] + hpart[t + 64]) * 0.125f;
    __syncthreads();
    {
        int e = t & 63, h = t >> 6;
        float acc = 0.f;
        const float* wk = Wk + (h * 32) * 64 + e;
#pragma unroll 8
        for (int dd = 0; dd < 32; ++dd) acc = fmaf(qv[h * 32 + dd], wk[dd * 64], acc);
        hpart[t] = acc;
    }
    __syncthreads();
    if (t < 64) qtv[t] = hpart[t] + hpart[t + 64];
    __syncthreads();
    if (t < 64) {
        int k = t >> 2, j = t & 3;
        reinterpret_cast<float*>(g_wts4 + b * 128)[(k * 8 + s) * 4 + j] = lng[t] * qtv[t];
    }
    if (t < 32) {
        float p1 = fmaf(lng[t + 32], qtv[t + 32], lng[t] * qtv[t]);
        float p0 = fmaf(lnb[t + 32], qtv[t + 32], lnb[t] * qtv[t]);
#pragma unroll
        for (int off = 16; off; off >>= 1) {
            p1 += __shfl_xor_sync(0xffffffffu, p1, off);
            p0 += __shfl_xor_sync(0xffffffffu, p0, off);
        }
        if (t == 0) { g_c1[b][s] = p1; g_c0[b][s] = p0; }
    }
}

// ---------------------------------------------------------------------------
__global__ void __launch_bounds__(128) k_init(
    const float* __restrict__ noise, const float* __restrict__ mu,
    const float* __restrict__ lsig,
    const float* __restrict__ lnsg, const float* __restrict__ lnsb,
    const float* __restrict__ Wq,   const float* __restrict__ Wk,
    const float* __restrict__ lng,  const float* __restrict__ lnb)
{
    __shared__ __align__(16) float snew[64], lns[64], qv[64], qtv[64], hpart[128];
    int bs = blockIdx.x, b = bs >> 3, s = bs & 7, t = threadIdx.x;
    if (t < 64) {
        int idx = s * 64 + t;
        float v = fmaf(__expf(lsig[idx]), noise[b * 512 + idx], mu[idx]);
        snew[t] = v;
        g_slots[b * 512 + idx] = v;
    }
    __syncthreads();
    prep_slot(b, s, t, snew, lns, qv, qtv, hpart, lnsg, lnsb, Wq, Wk, lng, lnb);
}

// ---------------------------------------------------------------------------
__device__ __forceinline__ void stage_tile(const float4* __restrict__ gsrc,
                                           unsigned sdst, int l)
{
#pragma unroll
    for (int j = 0; j < 16; ++j) {
        int flat = j * 32 + l;
        int row = flat >> 4, k = flat & 15;
        unsigned dst = sdst + (unsigned)((row * 16 + (k ^ (row & 15))) * 16);
        CPA(dst, gsrc + flat);
    }
    CPCOMMIT();
}

__device__ __forceinline__ void p1_epilogue(
    const ull* d2, ull sum2, ull sqa, ull sqb,
    const float* c0r, const float* c1r,
    float* gacc, float* bacc, float4* dst, int l)
{
    float slo, shi; F2UNPK(slo, shi, sum2);
    float sum = slo + shi;
    float qa0, qa1, qb0, qb1;
    F2UNPK(qa0, qa1, sqa); F2UNPK(qb0, qb1, sqb);
    float sq = (qa0 + qa1) + (qb0 + qb1);
    float m    = sum * (1.f / 64.f);
    float istd = rsqrtf(fmaf(sq, 1.f / 64.f, -m * m) + 1e-5f);
    float lo[8], mx = -3.4e38f;
#pragma unroll
    for (int s = 0; s < 8; ++s) {
        float dlo, dhi; F2UNPK(dlo, dhi, d2[s]);
        float d = dlo + dhi;
        lo[s] = fmaf(istd, fmaf(-m, c1r[s], d), c0r[s]);
        mx = fmaxf(mx, lo[s]);
    }
    float pr[8], ps = 0.f;
#pragma unroll
    for (int s = 0; s < 8; ++s) { pr[s] = __expf(lo[s] - mx); ps += pr[s]; }
    float rc  = 1.f / ps;
    float tmi = m * istd;
    float al[8];
#pragma unroll
    for (int s = 0; s < 8; ++s) {
        float a = fmaf(pr[s], rc, 1e-8f);   // softmax + EPS
        gacc[s] += a;
        bacc[s] = fmaf(a, tmi, bacc[s]);
        al[s]   = a * istd;
    }
    dst[l * 2 + 0] = make_float4(al[0], al[1], al[2], al[3]);
    dst[l * 2 + 1] = make_float4(al[4], al[5], al[6], al[7]);
}

__device__ __forceinline__ void p2_accum(
    const ulonglong2* xs2w, const float4* as4t, ull* p2, int g2, int e4)
{
#pragma unroll 4
    for (int r = 0; r < 32; ++r) {
        float4 av = as4t[r * 2 + g2];
        ulonglong2 xq = xs2w[r * 16 + (e4 ^ (r & 15))];
        ull a0, a1, a2, a3;
        F2PACK(a0, av.x, av.x); F2PACK(a1, av.y, av.y);
        F2PACK(a2, av.z, av.z); F2PACK(a3, av.w, av.w);
        F2FMA(p2[0], xq.x, a0); F2FMA(p2[1], xq.y, a0);
        F2FMA(p2[2], xq.x, a1); F2FMA(p2[3], xq.y, a1);
        F2FMA(p2[4], xq.x, a2); F2FMA(p2[5], xq.y, a2);
        F2FMA(p2[6], xq.x, a3); F2FMA(p2[7], xq.y, a3);
    }
}

// ---------------------------------------------------------------------------
// the big fused pass, paired phase-1 (round-13 winner) + PDL.
// ---------------------------------------------------------------------------
__global__ void __launch_bounds__(PASS_THREADS, 3) k_pass(const float4* __restrict__ x4)
{
    extern __shared__ __align__(16) float4 smem[];
    float4* xs   = smem;
    float4* as4  = smem + 4096;
    float4* wts  = smem + 4608;
    float*  tail = (float*)(smem + 4736);   // 80 floats

    const int b = blockIdx.y;
    const int t = threadIdx.x;
    const int w = t >> 5, l = t & 31;

    unsigned smem_u32;
    { size_t a = __cvta_generic_to_shared(xs); smem_u32 = (unsigned)a; }
    const unsigned xs_base = smem_u32 + (unsigned)(w * 1024 * 16);

    // stage x tiles (input-only) BEFORE waiting on predecessor
    const float4* gwarp = x4 + ((size_t)b * NN + (size_t)blockIdx.x * 512 + w * 128) * 16;
    stage_tile(gwarp,       xs_base,        l);   // t0 -> buf0
    stage_tile(gwarp + 512, xs_base + 8192, l);   // t1 -> buf1

    GRID_WAIT();            // predecessor (k_init / k_update) results visible
    wts[t] = g_wts4[b * 128 + t];
    if (t < 8)  tail[t]     = g_c0[b][t];
    if (t >= 8 && t < 16) tail[t] = g_c1[b][t - 8];
    GRID_LAUNCH_DEP();      // let the next k_update start staging weights
    __syncthreads();

    float c0r[8], c1r[8], gacc[8], bacc[8];
    ull p2[8];
#pragma unroll
    for (int s = 0; s < 8; ++s) {
        c0r[s] = tail[s]; c1r[s] = tail[8 + s];
        gacc[s] = 0.f; bacc[s] = 0.f; p2[s] = 0ULL;
    }

    const ulonglong2* wt2 = reinterpret_cast<const ulonglong2*>(wts);
    float4* as4w = as4 + w * 128;
    const int g2 = l >> 4, e4 = l & 15;
    const ulonglong2* xsA = reinterpret_cast<const ulonglong2*>(xs + w * 1024);
    const ulonglong2* xsB = reinterpret_cast<const ulonglong2*>(xs + w * 1024 + 512);

#pragma unroll
    for (int pr = 0; pr < 2; ++pr) {
        WAITG(0);
        __syncwarp();

        {
            ull dA[8], dB[8];
#pragma unroll
            for (int s = 0; s < 8; ++s) { dA[s] = 0ULL; dB[s] = 0ULL; }
            ull sumA = 0ULL, sumB = 0ULL, sqaA = 0ULL, sqaB = 0ULL, sqbA = 0ULL, sqbB = 0ULL;
            const int rb = l * 16, ro = l & 15;
#pragma unroll
            for (int k = 0; k < 16; ++k) {
                ulonglong2 vA = xsA[rb + (k ^ ro)];
                ulonglong2 vB = xsB[rb + (k ^ ro)];
                ull tv;
                F2ADD(tv, vA.x, vA.y); F2ADD(sumA, sumA, tv);
                F2ADD(tv, vB.x, vB.y); F2ADD(sumB, sumB, tv);
                F2FMA(sqaA, vA.x, vA.x); F2FMA(sqbA, vA.y, vA.y);
                F2FMA(sqaB, vB.x, vB.x); F2FMA(sqbB, vB.y, vB.y);
#pragma unroll
                for (int s = 0; s < 8; ++s) {
                    ulonglong2 wv = wt2[k * 8 + s];
                    F2FMA(dA[s], vA.x, wv.x); F2FMA(dA[s], vA.y, wv.y);
                    F2FMA(dB[s], vB.x, wv.x); F2FMA(dB[s], vB.y, wv.y);
                }
            }
            p1_epilogue(dA, sumA, sqaA, sqbA, c0r, c1r, gacc, bacc, as4w,      l);
            p1_epilogue(dB, sumB, sqaB, sqbB, c0r, c1r, gacc, bacc, as4w + 64, l);
        }
        __syncwarp();

        p2_accum(xsA, as4w, p2, g2, e4);
        if (pr == 0) stage_tile(gwarp + 2 * 512, xs_base, l);        // t2 -> buf0
        p2_accum(xsB, as4w + 64, p2, g2, e4);
        if (pr == 0) stage_tile(gwarp + 3 * 512, xs_base + 8192, l); // t3 -> buf1
        __syncwarp();
    }

#pragma unroll
    for (int s = 0; s < 8; ++s) {
        float gv = gacc[s], bv = bacc[s];
#pragma unroll
        for (int off = 16; off; off >>= 1) {
            gv += __shfl_xor_sync(0xffffffffu, gv, off);
            bv += __shfl_xor_sync(0xffffffffu, bv, off);
        }
        if (l == 0) { tail[16 + w * 8 + s] = gv; tail[48 + w * 8 + s] = bv; }
    }
    __syncthreads();

    float4* red4 = xs;
#pragma unroll
    for (int ss = 0; ss < 4; ++ss) {
        float x0, x1, x2, x3;
        F2UNPK(x0, x1, p2[2 * ss]);
        F2UNPK(x2, x3, p2[2 * ss + 1]);
        red4[w * 128 + (4 * g2 + ss) * 16 + e4] = make_float4(x0, x1, x2, x3);
    }
    __syncthreads();

    float4* gp4 = g_part4 + ((size_t)(b * NBLKX + blockIdx.x)) * 132;
    {
        float4 a = red4[t], bb2 = red4[128 + t], c = red4[256 + t], d = red4[384 + t];
        float4 o;
        o.x = ((a.x + bb2.x) + c.x) + d.x;
        o.y = ((a.y + bb2.y) + c.y) + d.y;
        o.z = ((a.z + bb2.z) + c.z) + d.z;
        o.w = ((a.w + bb2.w) + c.w) + d.w;
        gp4[t] = o;
    }
    if (t < 16) {
        const float* src = tail + 16 + (t >= 8 ? 32 : 0) + (t & 7);
        float v = ((src[0] + src[8]) + src[16]) + src[24];
        reinterpret_cast<float*>(gp4)[512 + (t >= 8 ? 8 : 0) + (t & 7)] = v;
    }
}

// ---------------------------------------------------------------------------
// slot update + PDL: stage ALL weights (input-only) before griddepcontrol.wait
// ---------------------------------------------------------------------------
__global__ void __launch_bounds__(256) k_update(
    const float* __restrict__ lng,  const float* __restrict__ lnb,
    const float* __restrict__ lnsg, const float* __restrict__ lnsb,
    const float* __restrict__ lnmg, const float* __restrict__ lnmb,
    const float* __restrict__ Wq,   const float* __restrict__ Wk,
    const float* __restrict__ Wv,
    const float* __restrict__ W_ih, const float* __restrict__ W_hh,
    const float* __restrict__ b_ih, const float* __restrict__ b_hh,
    const float* __restrict__ W1,   const float* __restrict__ b1,
    const float* __restrict__ W2,   const float* __restrict__ b2,
    float* __restrict__ out, int last)
{
    extern __shared__ __align__(16) float4 smu[];
    float4* sWv  = smu;
    float4* sWih = smu + 1024;
    float4* sWhh = smu + 4096;
    float4* sW1  = smu + 7168;
    float4* sW2  = smu + 9216;
    float4* sWq  = smu + 11264;
    float4* sWk  = smu + 12288;
    float*  sPar = (float*)(smu + 13312);

    float *sBih = sPar, *sBhh = sPar + 192, *sB1 = sPar + 384, *sB2 = sPar + 512;
    float *sLng = sPar + 576, *sLnb = sPar + 640, *sLnsg = sPar + 704;
    float *sLnsb = sPar + 768, *sLnmg = sPar + 832, *sLnmb = sPar + 896;

    const int bx = blockIdx.x, b0 = bx >> 3, s = bx & 7;
    const int t = threadIdx.x;
    const int hb = t >> 7, t2 = t & 127;
    const int b = b0 + 16 * hb;

    float* act = (float*)(smu + 13552) + hb * ACTF;
    float *P = act, *Uv = act + 64, *upds = act + 128, *slp = act + 192;
    float *updh = act + 256, *mln = act + 320, *snew = act + 384;
    float *lns = act + 448, *qv = act + 512, *qtv = act + 576;
    float *gi = act + 640, *gh = act + 832, *hhs = act + 1024, *hpart = act + 1152;
    float4* pg4 = (float4*)(act + 640);   // aliases gi (consumed before D)
    float*  sred = act + 1280;
    float*  sS   = act + 1288;

    unsigned sb;
    { size_t a = __cvta_generic_to_shared(smu); sb = (unsigned)a; }
    const unsigned parU = sb + 13312u * 16u;

    // ---- stage ALL weights (independent of predecessor) ----
    for (int i = t; i < 1024; i += 256) CPA(sb + i * 16, (const float4*)Wv + i);
    if (t < 48) CPA(parU + t * 16,          (const float4*)b_ih + t);
    if (t >= 48 && t < 96)  CPA(parU + t * 16, (const float4*)b_hh + (t - 48));
    if (t >= 96 && t < 128) CPA(parU + t * 16, (const float4*)b1 + (t - 96));
    if (t >= 128 && t < 144) CPA(parU + t * 16, (const float4*)b2 + (t - 128));
    if (t >= 144 && t < 160) CPA(parU + t * 16, (const float4*)lng + (t - 144));
    if (t >= 160 && t < 176) CPA(parU + t * 16, (const float4*)lnb + (t - 160));
    if (t >= 176 && t < 192) CPA(parU + t * 16, (const float4*)lnsg + (t - 176));
    if (t >= 192 && t < 208) CPA(parU + t * 16, (const float4*)lnsb + (t - 192));
    if (t >= 208 && t < 224) CPA(parU + t * 16, (const float4*)lnmg + (t - 208));
    if (t >= 224 && t < 240) CPA(parU + t * 16, (const float4*)lnmb + (t - 224));
    CPCOMMIT();
    for (int i = t; i < 3072; i += 256) CPA(sb + (1024 + i) * 16, (const float4*)W_ih + i);
    CPCOMMIT();
    for (int i = t; i < 3072; i += 256) CPA(sb + (4096 + i) * 16, (const float4*)W_hh + i);
    CPCOMMIT();
    for (int i = t; i < 2048; i += 256) CPA(sb + (7168 + i) * 16, (const float4*)W1 + i);
    CPCOMMIT();
    for (int i = t; i < 2048; i += 256) CPA(sb + (9216 + i) * 16, (const float4*)W2 + i);
    CPCOMMIT();
    for (int i = t; i < 1024; i += 256) CPA(sb + (11264 + i) * 16, (const float4*)Wq + i);
    CPCOMMIT();
    for (int i = t; i < 1024; i += 256) CPA(sb + (12288 + i) * 16, (const float4*)Wk + i);
    CPCOMMIT();

    GRID_LAUNCH_DEP();      // next k_pass may start staging x
    GRID_WAIT();            // k_pass partials now visible

    // ---- A: coalesced fixed-order reduce of 32 records for this (b,s) ----
    {
        const float4* pb4 = g_part4 + (size_t)b * NBLKX * 132;
        if (t2 < 64) {
            int e4 = t2 & 15, grp = t2 >> 4;
            const float4* src = pb4 + (size_t)grp * 8 * 132 + s * 16 + e4;
            float4 acc = make_float4(0.f, 0.f, 0.f, 0.f);
#pragma unroll
            for (int j = 0; j < 8; ++j) {
                float4 v = src[(size_t)j * 132];
                acc.x += v.x; acc.y += v.y; acc.z += v.z; acc.w += v.w;
            }
            pg4[grp * 16 + e4] = acc;
        } else if (t2 < 72) {
            int which = (t2 - 64) >> 2;
            int grp = (t2 - 64) & 3;
            const float* src = reinterpret_cast<const float*>(pb4)
                             + (size_t)grp * 8 * PREC + 512 + which * 8 + s;
            float acc = 0.f;
#pragma unroll
            for (int j = 0; j < 8; ++j) acc += src[(size_t)j * PREC];
            sred[t2 - 64] = acc;
        }
        if (t2 >= 64) slp[t2 - 64] = g_slots[b * 512 + s * 64 + (t2 - 64)];
    }

    WAITG(6);            // G0 (Wv + params) complete
    __syncthreads();
    if (t2 < 16) {
        float4 a = pg4[t2], bg = pg4[16 + t2], c = pg4[32 + t2], d = pg4[48 + t2];
        float4 o;
        o.x = ((a.x + bg.x) + c.x) + d.x;
        o.y = ((a.y + bg.y) + c.y) + d.y;
        o.z = ((a.z + bg.z) + c.z) + d.z;
        o.w = ((a.w + bg.w) + c.w) + d.w;
        reinterpret_cast<float4*>(P)[t2] = o;
    }
    if (t2 == 0) sS[0] = ((sred[0] + sred[1]) + sred[2]) + sred[3];
    if (t2 == 1) sS[1] = ((sred[4] + sred[5]) + sred[6]) + sred[7];
    __syncthreads();

    if (t2 < 64) Uv[t2] = fmaf(sLng[t2], P[t2] - sS[1], sLnb[t2] * sS[0]) / sS[0];
    __syncthreads();

    {
        int dd = t2 & 63, h = t2 >> 6;
        float r = dot8x4((const float4*)Uv + h * 8, sWv + dd * 16 + h * 8);
        __syncthreads();
        hpart[t2] = r;
    }
    __syncthreads();
    if (t2 < 64) upds[t2] = hpart[t2] + hpart[t2 + 64];
    WAITG(4);            // W_ih, W_hh complete
    __syncthreads();

#pragma unroll
    for (int k = 0; k < 3; ++k) {
        int id = t2 + 128 * k;
        if (id < 192) {
            gi[id] = dot16x4((const float4*)upds, sWih + id * 16, sBih[id]);
        } else {
            int j = id - 192;
            gh[j] = dot16x4((const float4*)slp, sWhh + j * 16, sBhh[j]);
        }
    }
    __syncthreads();

    if (t2 < 64) {
        float r = sigm(gi[t2]      + gh[t2]);
        float z = sigm(gi[64 + t2] + gh[64 + t2]);
        float n = tanhf(fmaf(r, gh[128 + t2], gi[128 + t2]));
        updh[t2] = fmaf(z, slp[t2] - n, n);
    }
    __syncthreads();

    ln64_warp(updh, mln, sLnmg, sLnmb, t2);
    WAITG(3);            // W1 complete
    __syncthreads();

    hhs[t2] = fmaxf(dot16x4((const float4*)mln, sW1 + t2 * 16, sB1[t2]), 0.f);
    WAITG(2);            // W2 complete
    __syncthreads();

    {
        int dd = t2 & 63, h = t2 >> 6;
        float r = dot16x4((const float4*)hhs + h * 16, sW2 + dd * 32 + h * 16, 0.f);
        __syncthreads();
        hpart[t2] = r;
    }
    __syncthreads();
    if (t2 < 64) {
        float v = updh[t2] + sB2[t2] + (hpart[t2] + hpart[t2 + 64]);
        snew[t2] = v;
        g_slots[b * 512 + s * 64 + t2] = v;
        if (last) out[b * 512 + s * 64 + t2] = v;
    }
    WAITG(0);            // Wq, Wk complete
    __syncthreads();

    if (!last)
        prep_slot(b, s, t2, snew, lns, qv, qtv, hpart, sLnsg, sLnsb,
                  (const float*)sWq, (const float*)sWk, sLng, sLnb);
}

// ---------------------------------------------------------------------------
extern "C" void kernel_launch(void* const* d_in, const int* in_sizes, int n_in,
                              void* d_out, int out_size)
{
    const float* x     = (const float*)d_in[0];
    const float* noise = (const float*)d_in[1];
    const float* mu    = (const float*)d_in[2];
    const float* lsig  = (const float*)d_in[3];
    const float* lng   = (const float*)d_in[4];
    const float* lnb   = (const float*)d_in[5];
    const float* lnsg  = (const float*)d_in[6];
    const float* lnsb  = (const float*)d_in[7];
    const float* lnmg  = (const float*)d_in[8];
    const float* lnmb  = (const float*)d_in[9];
    const float* Wq    = (const float*)d_in[10];
    const float* Wk    = (const float*)d_in[11];
    const float* Wv    = (const float*)d_in[12];
    const float* W_ih  = (const float*)d_in[13];
    const float* W_hh  = (const float*)d_in[14];
    const float* b_ih  = (const float*)d_in[15];
    const float* b_hh  = (const float*)d_in[16];
    const float* W1    = (const float*)d_in[17];
    const float* b1    = (const float*)d_in[18];
    const float* W2    = (const float*)d_in[19];
    const float* b2    = (const float*)d_in[20];
    float* out = (float*)d_out;

    cudaFuncSetAttribute(k_pass, cudaFuncAttributeMaxDynamicSharedMemorySize, SMEM_BYTES);
    cudaFuncSetAttribute(k_update, cudaFuncAttributeMaxDynamicSharedMemorySize, UPD_SMEM);

    k_init<<<BB * SS, 128>>>(noise, mu, lsig, lnsg, lnsb, Wq, Wk, lng, lnb);

    cudaLaunchAttribute pdl[1];
    pdl[0].id = cudaLaunchAttributeProgrammaticStreamSerialization;
    pdl[0].val.programmaticStreamSerializationAllowed = 1;

    for (int it = 0; it < 3; ++it) {
        {
            cudaLaunchConfig_t cfg = {};
            cfg.gridDim = dim3(NBLKX, BB);
            cfg.blockDim = dim3(PASS_THREADS);
            cfg.dynamicSmemBytes = SMEM_BYTES;
            cfg.stream = 0;
            cfg.attrs = pdl;
            cfg.numAttrs = 1;
            cudaLaunchKernelEx(&cfg, k_pass, (const float4*)x);
        }
        {
            cudaLaunchConfig_t cfg = {};
            cfg.gridDim = dim3(128);
            cfg.blockDim = dim3(256);
            cfg.dynamicSmemBytes = UPD_SMEM;
            cfg.stream = 0;
            cfg.attrs = pdl;
            cfg.numAttrs = 1;
            cudaLaunchKernelEx(&cfg, k_update, lng, lnb, lnsg, lnsb, lnmg, lnmb,
                               Wq, Wk, Wv, W_ih, W_hh, b_ih, b_hh,
                               W1, b1, W2, b2, out, it == 2);
        }
    }
}

// round 16
// speedup vs baseline: 1.0837x; 1.0072x over previous
#include <cuda_runtime.h>

// ---------------------------------------------------------------------------
// SlotAttention fused. B=32, N=16384, S=8, D=64, H=128, ITERS=3.
// k_pass: per-warp cp.async ring-2, paired phase-1 (round-12/13 winner) + PDL.
// k_update: 128 blocks x 256 threads, weights staged to smem, two (b,s)
//           pairs concurrent in half-blocks + PDL.
// k_init: NOW stages Wq/Wk into smem via cp.async overlapped with the
//           noise/slot-init phase (was cold-DRAM serial dots).
// ---------------------------------------------------------------------------

#define BB 32
#define NN 16384
#define SS 8
#define DD 64
#define HH 128
#define NBLKX 32                 // pass blocks per batch (512 rows each)
#define PREC 528                 // floats per record: 512 Pacc + 8 Sg + 8 Sb
#define PASS_THREADS 128
// k_pass smem: xs 4096f4 + as4 512f4 + wts 128f4 + tail 80f = 76096 -> 76160
#define SMEM_BYTES 76160
#define ACTF 1344
#define UPD_SMEM ((13552 + 2 * (ACTF / 4)) * 16)   // 227584 bytes
#define INIT_SMEM (2048 * 16 + 1536)               // sWq+sWk (32KB) + scratch

typedef unsigned long long ull;

__device__ float  g_slots[BB * SS * DD];
__device__ float4 g_wts4[BB * 128];          // [b][k=0..15][s=0..7]
__device__ float  g_c0[BB][SS];
__device__ float  g_c1[BB][SS];
__device__ float4 g_part4[(size_t)BB * NBLKX * 132];

#define F2FMA(d, a, b) asm("fma.rn.f32x2 %0, %1, %2, %0;" : "+l"(d) : "l"(a), "l"(b))
#define F2ADD(d, a, b) asm("add.rn.f32x2 %0, %1, %2;" : "=l"(d) : "l"(a), "l"(b))
#define F2PACK(v, lo, hi) asm("mov.b64 %0, {%1, %2};" : "=l"(v) : "f"(lo), "f"(hi))
#define F2UNPK(lo, hi, v) asm("mov.b64 {%0, %1}, %2;" : "=f"(lo), "=f"(hi) : "l"(v))

#define CPA(dst, src) asm volatile("cp.async.cg.shared.global [%0], [%1], 16;" \
                                   :: "r"(dst), "l"(src))
#define CPCOMMIT() asm volatile("cp.async.commit_group;")
#define WAITG(n) asm volatile("cp.async.wait_group " #n ";" ::: "memory")
#define GRID_WAIT() asm volatile("griddepcontrol.wait;" ::: "memory")
#define GRID_LAUNCH_DEP() asm volatile("griddepcontrol.launch_dependents;" ::: "memory")

__device__ __forceinline__ float sigm(float x) { return 1.f / (1.f + __expf(-x)); }

__device__ __forceinline__ float dot16x4(const float4* a, const float4* w, float bias) {
    float a0 = 0.f, a1 = 0.f, a2 = 0.f, a3 = 0.f;
#pragma unroll
    for (int e = 0; e < 4; ++e) {
        float4 x0 = a[e],      w0 = w[e];
        float4 x1 = a[e + 4],  w1 = w[e + 4];
        float4 x2 = a[e + 8],  w2 = w[e + 8];
        float4 x3 = a[e + 12], w3 = w[e + 12];
        a0 = fmaf(x0.x, w0.x, fmaf(x0.y, w0.y, fmaf(x0.z, w0.z, fmaf(x0.w, w0.w, a0))));
        a1 = fmaf(x1.x, w1.x, fmaf(x1.y, w1.y, fmaf(x1.z, w1.z, fmaf(x1.w, w1.w, a1))));
        a2 = fmaf(x2.x, w2.x, fmaf(x2.y, w2.y, fmaf(x2.z, w2.z, fmaf(x2.w, w2.w, a2))));
        a3 = fmaf(x3.x, w3.x, fmaf(x3.y, w3.y, fmaf(x3.z, w3.z, fmaf(x3.w, w3.w, a3))));
    }
    return bias + ((a0 + a1) + (a2 + a3));
}
__device__ __forceinline__ float dot8x4(const float4* a, const float4* w) {
    float a0 = 0.f, a1 = 0.f;
#pragma unroll
    for (int e = 0; e < 4; ++e) {
        float4 x0 = a[e],     w0 = w[e];
        float4 x1 = a[e + 4], w1 = w[e + 4];
        a0 = fmaf(x0.x, w0.x, fmaf(x0.y, w0.y, fmaf(x0.z, w0.z, fmaf(x0.w, w0.w, a0))));
        a1 = fmaf(x1.x, w1.x, fmaf(x1.y, w1.y, fmaf(x1.z, w1.z, fmaf(x1.w, w1.w, a1))));
    }
    return a0 + a1;
}

__device__ __forceinline__ void ln64_warp(const float* in, float* out,
                                          const float* g,
                                          const float* bt, int t) {
    if (t < 32) {
        float v0 = in[t], v1 = in[t + 32];
        float sum = v0 + v1;
        float sq  = fmaf(v0, v0, v1 * v1);
#pragma unroll
        for (int off = 16; off; off >>= 1) {
            sum += __shfl_xor_sync(0xffffffffu, sum, off);
            sq  += __shfl_xor_sync(0xffffffffu, sq,  off);
        }
        float m    = sum * (1.f / 64.f);
        float istd = rsqrtf(fmaf(sq, 1.f / 64.f, -m * m) + 1e-5f);
        out[t]      = fmaf((v0 - m) * istd, g[t],      bt[t]);
        out[t + 32] = fmaf((v1 - m) * istd, g[t + 32], bt[t + 32]);
    }
}

// ---------------------------------------------------------------------------
__device__ __forceinline__ void prep_slot(
    int b, int s, int t,
    const float* snew, float* lns, float* qv, float* qtv, float* hpart,
    const float* lnsg, const float* lnsb,
    const float* Wq,   const float* Wk,
    const float* lng,  const float* lnb)
{
    ln64_warp(snew, lns, lnsg, lnsb, t);
    __syncthreads();
    {
        int dd = t & 63, h = t >> 6;
        const float4* wr = (const float4*)(Wq + dd * 64) + h * 8;
        const float4* lv = (const float4*)lns + h * 8;
        hpart[t] = dot8x4(lv, wr);
    }
    __syncthreads();
    if (t < 64) qv[t] = (hpart[t] + hpart[t + 64]) * 0.125f;
    __syncthreads();
    {
        int e = t & 63, h = t >> 6;
        float acc = 0.f;
        const float* wk = Wk + (h * 32) * 64 + e;
#pragma unroll 8
        for (int dd = 0; dd < 32; ++dd) acc = fmaf(qv[h * 32 + dd], wk[dd * 64], acc);
        hpart[t] = acc;
    }
    __syncthreads();
    if (t < 64) qtv[t] = hpart[t] + hpart[t + 64];
    __syncthreads();
    if (t < 64) {
        int k = t >> 2, j = t & 3;
        reinterpret_cast<float*>(g_wts4 + b * 128)[(k * 8 + s) * 4 + j] = lng[t] * qtv[t];
    }
    if (t < 32) {
        float p1 = fmaf(lng[t + 32], qtv[t + 32], lng[t] * qtv[t]);
        float p0 = fmaf(lnb[t + 32], qtv[t + 32], lnb[t] * qtv[t]);
#pragma unroll
        for (int off = 16; off; off >>= 1) {
            p1 += __shfl_xor_sync(0xffffffffu, p1, off);
            p0 += __shfl_xor_sync(0xffffffffu, p0, off);
        }
        if (t == 0) { g_c1[b][s] = p1; g_c0[b][s] = p0; }
    }
}

// ---------------------------------------------------------------------------
// k_init: stage Wq/Wk into smem via cp.async, overlapped with slot init.
// ---------------------------------------------------------------------------
__global__ void __launch_bounds__(128) k_init(
    const float* __restrict__ noise, const float* __restrict__ mu,
    const float* __restrict__ lsig,
    const float* __restrict__ lnsg, const float* __restrict__ lnsb,
    const float* __restrict__ Wq,   const float* __restrict__ Wk,
    const float* __restrict__ lng,  const float* __restrict__ lnb)
{
    extern __shared__ __align__(16) float4 smi[];
    float4* sWq = smi;
    float4* sWk = smi + 1024;
    float*  scr = (float*)(smi + 2048);
    float *snew = scr, *lns = scr + 64, *qv = scr + 128, *qtv = scr + 192;
    float *hpart = scr + 256;   // 128

    int bs = blockIdx.x, b = bs >> 3, s = bs & 7, t = threadIdx.x;

    unsigned sb;
    { size_t a = __cvta_generic_to_shared(smi); sb = (unsigned)a; }
    for (int i = t; i < 1024; i += 128) CPA(sb + i * 16, (const float4*)Wq + i);
    CPCOMMIT();
    for (int i = t; i < 1024; i += 128) CPA(sb + (1024 + i) * 16, (const float4*)Wk + i);
    CPCOMMIT();

    if (t < 64) {
        int idx = s * 64 + t;
        float v = fmaf(__expf(lsig[idx]), noise[b * 512 + idx], mu[idx]);
        snew[t] = v;
        g_slots[b * 512 + idx] = v;
    }
    WAITG(0);
    __syncthreads();
    prep_slot(b, s, t, snew, lns, qv, qtv, hpart, lnsg, lnsb,
              (const float*)sWq, (const float*)sWk, lng, lnb);
}

// ---------------------------------------------------------------------------
__device__ __forceinline__ void stage_tile(const float4* __restrict__ gsrc,
                                           unsigned sdst, int l)
{
#pragma unroll
    for (int j = 0; j < 16; ++j) {
        int flat = j * 32 + l;
        int row = flat >> 4, k = flat & 15;
        unsigned dst = sdst + (unsigned)((row * 16 + (k ^ (row & 15))) * 16);
        CPA(dst, gsrc + flat);
    }
    CPCOMMIT();
}

__device__ __forceinline__ void p1_epilogue(
    const ull* d2, ull sum2, ull sqa, ull sqb,
    const float* c0r, const float* c1r,
    float* gacc, float* bacc, float4* dst, int l)
{
    float slo, shi; F2UNPK(slo, shi, sum2);
    float sum = slo + shi;
    float qa0, qa1, qb0, qb1;
    F2UNPK(qa0, qa1, sqa); F2UNPK(qb0, qb1, sqb);
    float sq = (qa0 + qa1) + (qb0 + qb1);
    float m    = sum * (1.f / 64.f);
    float istd = rsqrtf(fmaf(sq, 1.f / 64.f, -m * m) + 1e-5f);
    float lo[8], mx = -3.4e38f;
#pragma unroll
    for (int s = 0; s < 8; ++s) {
        float dlo, dhi; F2UNPK(dlo, dhi, d2[s]);
        float d = dlo + dhi;
        lo[s] = fmaf(istd, fmaf(-m, c1r[s], d), c0r[s]);
        mx = fmaxf(mx, lo[s]);
    }
    float pr[8], ps = 0.f;
#pragma unroll
    for (int s = 0; s < 8; ++s) { pr[s] = __expf(lo[s] - mx); ps += pr[s]; }
    float rc  = 1.f / ps;
    float tmi = m * istd;
    float al[8];
#pragma unroll
    for (int s = 0; s < 8; ++s) {
        float a = fmaf(pr[s], rc, 1e-8f);   // softmax + EPS
        gacc[s] += a;
        bacc[s] = fmaf(a, tmi, bacc[s]);
        al[s]   = a * istd;
    }
    dst[l * 2 + 0] = make_float4(al[0], al[1], al[2], al[3]);
    dst[l * 2 + 1] = make_float4(al[4], al[5], al[6], al[7]);
}

__device__ __forceinline__ void p2_accum(
    const ulonglong2* xs2w, const float4* as4t, ull* p2, int g2, int e4)
{
#pragma unroll 4
    for (int r = 0; r < 32; ++r) {
        float4 av = as4t[r * 2 + g2];
        ulonglong2 xq = xs2w[r * 16 + (e4 ^ (r & 15))];
        ull a0, a1, a2, a3;
        F2PACK(a0, av.x, av.x); F2PACK(a1, av.y, av.y);
        F2PACK(a2, av.z, av.z); F2PACK(a3, av.w, av.w);
        F2FMA(p2[0], xq.x, a0); F2FMA(p2[1], xq.y, a0);
        F2FMA(p2[2], xq.x, a1); F2FMA(p2[3], xq.y, a1);
        F2FMA(p2[4], xq.x, a2); F2FMA(p2[5], xq.y, a2);
        F2FMA(p2[6], xq.x, a3); F2FMA(p2[7], xq.y, a3);
    }
}

// ---------------------------------------------------------------------------
// the big fused pass, paired phase-1 + PDL (round-15 winner, unchanged).
// ---------------------------------------------------------------------------
__global__ void __launch_bounds__(PASS_THREADS, 3) k_pass(const float4* __restrict__ x4)
{
    extern __shared__ __align__(16) float4 smem[];
    float4* xs   = smem;
    float4* as4  = smem + 4096;
    float4* wts  = smem + 4608;
    float*  tail = (float*)(smem + 4736);   // 80 floats

    const int b = blockIdx.y;
    const int t = threadIdx.x;
    const int w = t >> 5, l = t & 31;

    unsigned smem_u32;
    { size_t a = __cvta_generic_to_shared(xs); smem_u32 = (unsigned)a; }
    const unsigned xs_base = smem_u32 + (unsigned)(w * 1024 * 16);

    const float4* gwarp = x4 + ((size_t)b * NN + (size_t)blockIdx.x * 512 + w * 128) * 16;
    stage_tile(gwarp,       xs_base,        l);   // t0 -> buf0
    stage_tile(gwarp + 512, xs_base + 8192, l);   // t1 -> buf1

    GRID_WAIT();
    wts[t] = g_wts4[b * 128 + t];
    if (t < 8)  tail[t]     = g_c0[b][t];
    if (t >= 8 && t < 16) tail[t] = g_c1[b][t - 8];
    GRID_LAUNCH_DEP();
    __syncthreads();

    float c0r[8], c1r[8], gacc[8], bacc[8];
    ull p2[8];
#pragma unroll
    for (int s = 0; s < 8; ++s) {
        c0r[s] = tail[s]; c1r[s] = tail[8 + s];
        gacc[s] = 0.f; bacc[s] = 0.f; p2[s] = 0ULL;
    }

    const ulonglong2* wt2 = reinterpret_cast<const ulonglong2*>(wts);
    float4* as4w = as4 + w * 128;
    const int g2 = l >> 4, e4 = l & 15;
    const ulonglong2* xsA = reinterpret_cast<const ulonglong2*>(xs + w * 1024);
    const ulonglong2* xsB = reinterpret_cast<const ulonglong2*>(xs + w * 1024 + 512);

#pragma unroll
    for (int pr = 0; pr < 2; ++pr) {
        WAITG(0);
        __syncwarp();

        {
            ull dA[8], dB[8];
#pragma unroll
            for (int s = 0; s < 8; ++s) { dA[s] = 0ULL; dB[s] = 0ULL; }
            ull sumA = 0ULL, sumB = 0ULL, sqaA = 0ULL, sqaB = 0ULL, sqbA = 0ULL, sqbB = 0ULL;
            const int rb = l * 16, ro = l & 15;
#pragma unroll
            for (int k = 0; k < 16; ++k) {
                ulonglong2 vA = xsA[rb + (k ^ ro)];
                ulonglong2 vB = xsB[rb + (k ^ ro)];
                ull tv;
                F2ADD(tv, vA.x, vA.y); F2ADD(sumA, sumA, tv);
                F2ADD(tv, vB.x, vB.y); F2ADD(sumB, sumB, tv);
                F2FMA(sqaA, vA.x, vA.x); F2FMA(sqbA, vA.y, vA.y);
                F2FMA(sqaB, vB.x, vB.x); F2FMA(sqbB, vB.y, vB.y);
#pragma unroll
                for (int s = 0; s < 8; ++s) {
                    ulonglong2 wv = wt2[k * 8 + s];
                    F2FMA(dA[s], vA.x, wv.x); F2FMA(dA[s], vA.y, wv.y);
                    F2FMA(dB[s], vB.x, wv.x); F2FMA(dB[s], vB.y, wv.y);
                }
            }
            p1_epilogue(dA, sumA, sqaA, sqbA, c0r, c1r, gacc, bacc, as4w,      l);
            p1_epilogue(dB, sumB, sqaB, sqbB, c0r, c1r, gacc, bacc, as4w + 64, l);
        }
        __syncwarp();

        p2_accum(xsA, as4w, p2, g2, e4);
        if (pr == 0) stage_tile(gwarp + 2 * 512, xs_base, l);        // t2 -> buf0
        p2_accum(xsB, as4w + 64, p2, g2, e4);
        if (pr == 0) stage_tile(gwarp + 3 * 512, xs_base + 8192, l); // t3 -> buf1
        __syncwarp();
    }

#pragma unroll
    for (int s = 0; s < 8; ++s) {
        float gv = gacc[s], bv = bacc[s];
#pragma unroll
        for (int off = 16; off; off >>= 1) {
            gv += __shfl_xor_sync(0xffffffffu, gv, off);
            bv += __shfl_xor_sync(0xffffffffu, bv, off);
        }
        if (l == 0) { tail[16 + w * 8 + s] = gv; tail[48 + w * 8 + s] = bv; }
    }
    __syncthreads();

    float4* red4 = xs;
#pragma unroll
    for (int ss = 0; ss < 4; ++ss) {
        float x0, x1, x2, x3;
        F2UNPK(x0, x1, p2[2 * ss]);
        F2UNPK(x2, x3, p2[2 * ss + 1]);
        red4[w * 128 + (4 * g2 + ss) * 16 + e4] = make_float4(x0, x1, x2, x3);
    }
    __syncthreads();

    float4* gp4 = g_part4 + ((size_t)(b * NBLKX + blockIdx.x)) * 132;
    {
        float4 a = red4[t], bb2 = red4[128 + t], c = red4[256 + t], d = red4[384 + t];
        float4 o;
        o.x = ((a.x + bb2.x) + c.x) + d.x;
        o.y = ((a.y + bb2.y) + c.y) + d.y;
        o.z = ((a.z + bb2.z) + c.z) + d.z;
        o.w = ((a.w + bb2.w) + c.w) + d.w;
        gp4[t] = o;
    }
    if (t < 16) {
        const float* src = tail + 16 + (t >= 8 ? 32 : 0) + (t & 7);
        float v = ((src[0] + src[8]) + src[16]) + src[24];
        reinterpret_cast<float*>(gp4)[512 + (t >= 8 ? 8 : 0) + (t & 7)] = v;
    }
}

// ---------------------------------------------------------------------------
// slot update + PDL (round-15 winner, unchanged)
// ---------------------------------------------------------------------------
__global__ void __launch_bounds__(256) k_update(
    const float* __restrict__ lng,  const float* __restrict__ lnb,
    const float* __restrict__ lnsg, const float* __restrict__ lnsb,
    const float* __restrict__ lnmg, const float* __restrict__ lnmb,
    const float* __restrict__ Wq,   const float* __restrict__ Wk,
    const float* __restrict__ Wv,
    const float* __restrict__ W_ih, const float* __restrict__ W_hh,
    const float* __restrict__ b_ih, const float* __restrict__ b_hh,
    const float* __restrict__ W1,   const float* __restrict__ b1,
    const float* __restrict__ W2,   const float* __restrict__ b2,
    float* __restrict__ out, int last)
{
    extern __shared__ __align__(16) float4 smu[];
    float4* sWv  = smu;
    float4* sWih = smu + 1024;
    float4* sWhh = smu + 4096;
    float4* sW1  = smu + 7168;
    float4* sW2  = smu + 9216;
    float4* sWq  = smu + 11264;
    float4* sWk  = smu + 12288;
    float*  sPar = (float*)(smu + 13312);

    float *sBih = sPar, *sBhh = sPar + 192, *sB1 = sPar + 384, *sB2 = sPar + 512;
    float *sLng = sPar + 576, *sLnb = sPar + 640, *sLnsg = sPar + 704;
    float *sLnsb = sPar + 768, *sLnmg = sPar + 832, *sLnmb = sPar + 896;

    const int bx = blockIdx.x, b0 = bx >> 3, s = bx & 7;
    const int t = threadIdx.x;
    const int hb = t >> 7, t2 = t & 127;
    const int b = b0 + 16 * hb;

    float* act = (float*)(smu + 13552) + hb * ACTF;
    float *P = act, *Uv = act + 64, *upds = act + 128, *slp = act + 192;
    float *updh = act + 256, *mln = act + 320, *snew = act + 384;
    float *lns = act + 448, *qv = act + 512, *qtv = act + 576;
    float *gi = act + 640, *gh = act + 832, *hhs = act + 1024, *hpart = act + 1152;
    float4* pg4 = (float4*)(act + 640);   // aliases gi (consumed before D)
    float*  sred = act + 1280;
    float*  sS   = act + 1288;

    unsigned sb;
    { size_t a = __cvta_generic_to_shared(smu); sb = (unsigned)a; }
    const unsigned parU = sb + 13312u * 16u;

    for (int i = t; i < 1024; i += 256) CPA(sb + i * 16, (const float4*)Wv + i);
    if (t < 48) CPA(parU + t * 16,          (const float4*)b_ih + t);
    if (t >= 48 && t < 96)  CPA(parU + t * 16, (const float4*)b_hh + (t - 48));
    if (t >= 96 && t < 128) CPA(parU + t * 16, (const float4*)b1 + (t - 96));
    if (t >= 128 && t < 144) CPA(parU + t * 16, (const float4*)b2 + (t - 128));
    if (t >= 144 && t < 160) CPA(parU + t * 16, (const float4*)lng + (t - 144));
    if (t >= 160 && t < 176) CPA(parU + t * 16, (const float4*)lnb + (t - 160));
    if (t >= 176 && t < 192) CPA(parU + t * 16, (const float4*)lnsg + (t - 176));
    if (t >= 192 && t < 208) CPA(parU + t * 16, (const float4*)lnsb + (t - 192));
    if (t >= 208 && t < 224) CPA(parU + t * 16, (const float4*)lnmg + (t - 208));
    if (t >= 224 && t < 240) CPA(parU + t * 16, (const float4*)lnmb + (t - 224));
    CPCOMMIT();
    for (int i = t; i < 3072; i += 256) CPA(sb + (1024 + i) * 16, (const float4*)W_ih + i);
    CPCOMMIT();
    for (int i = t; i < 3072; i += 256) CPA(sb + (4096 + i) * 16, (const float4*)W_hh + i);
    CPCOMMIT();
    for (int i = t; i < 2048; i += 256) CPA(sb + (7168 + i) * 16, (const float4*)W1 + i);
    CPCOMMIT();
    for (int i = t; i < 2048; i += 256) CPA(sb + (9216 + i) * 16, (const float4*)W2 + i);
    CPCOMMIT();
    for (int i = t; i < 1024; i += 256) CPA(sb + (11264 + i) * 16, (const float4*)Wq + i);
    CPCOMMIT();
    for (int i = t; i < 1024; i += 256) CPA(sb + (12288 + i) * 16, (const float4*)Wk + i);
    CPCOMMIT();

    GRID_LAUNCH_DEP();
    GRID_WAIT();

    {
        const float4* pb4 = g_part4 + (size_t)b * NBLKX * 132;
        if (t2 < 64) {
            int e4 = t2 & 15, grp = t2 >> 4;
            const float4* src = pb4 + (size_t)grp * 8 * 132 + s * 16 + e4;
            float4 acc = make_float4(0.f, 0.f, 0.f, 0.f);
#pragma unroll
            for (int j = 0; j < 8; ++j) {
                float4 v = src[(size_t)j * 132];
                acc.x += v.x; acc.y += v.y; acc.z += v.z; acc.w += v.w;
            }
            pg4[grp * 16 + e4] = acc;
        } else if (t2 < 72) {
            int which = (t2 - 64) >> 2;
            int grp = (t2 - 64) & 3;
            const float* src = reinterpret_cast<const float*>(pb4)
                             + (size_t)grp * 8 * PREC + 512 + which * 8 + s;
            float acc = 0.f;
#pragma unroll
            for (int j = 0; j < 8; ++j) acc += src[(size_t)j * PREC];
            sred[t2 - 64] = acc;
        }
        if (t2 >= 64) slp[t2 - 64] = g_slots[b * 512 + s * 64 + (t2 - 64)];
    }

    WAITG(6);
    __syncthreads();
    if (t2 < 16) {
        float4 a = pg4[t2], bg = pg4[16 + t2], c = pg4[32 + t2], d = pg4[48 + t2];
        float4 o;
        o.x = ((a.x + bg.x) + c.x) + d.x;
        o.y = ((a.y + bg.y) + c.y) + d.y;
        o.z = ((a.z + bg.z) + c.z) + d.z;
        o.w = ((a.w + bg.w) + c.w) + d.w;
        reinterpret_cast<float4*>(P)[t2] = o;
    }
    if (t2 == 0) sS[0] = ((sred[0] + sred[1]) + sred[2]) + sred[3];
    if (t2 == 1) sS[1] = ((sred[4] + sred[5]) + sred[6]) + sred[7];
    __syncthreads();

    if (t2 < 64) Uv[t2] = fmaf(sLng[t2], P[t2] - sS[1], sLnb[t2] * sS[0]) / sS[0];
    __syncthreads();

    {
        int dd = t2 & 63, h = t2 >> 6;
        float r = dot8x4((const float4*)Uv + h * 8, sWv + dd * 16 + h * 8);
        __syncthreads();
        hpart[t2] = r;
    }
    __syncthreads();
    if (t2 < 64) upds[t2] = hpart[t2] + hpart[t2 + 64];
    WAITG(4);
    __syncthreads();

#pragma unroll
    for (int k = 0; k < 3; ++k) {
        int id = t2 + 128 * k;
        if (id < 192) {
            gi[id] = dot16x4((const float4*)upds, sWih + id * 16, sBih[id]);
        } else {
            int j = id - 192;
            gh[j] = dot16x4((const float4*)slp, sWhh + j * 16, sBhh[j]);
        }
    }
    __syncthreads();

    if (t2 < 64) {
        float r = sigm(gi[t2]      + gh[t2]);
        float z = sigm(gi[64 + t2] + gh[64 + t2]);
        float n = tanhf(fmaf(r, gh[128 + t2], gi[128 + t2]));
        updh[t2] = fmaf(z, slp[t2] - n, n);
    }
    __syncthreads();

    ln64_warp(updh, mln, sLnmg, sLnmb, t2);
    WAITG(3);
    __syncthreads();

    hhs[t2] = fmaxf(dot16x4((const float4*)mln, sW1 + t2 * 16, sB1[t2]), 0.f);
    WAITG(2);
    __syncthreads();

    {
        int dd = t2 & 63, h = t2 >> 6;
        float r = dot16x4((const float4*)hhs + h * 16, sW2 + dd * 32 + h * 16, 0.f);
        __syncthreads();
        hpart[t2] = r;
    }
    __syncthreads();
    if (t2 < 64) {
        float v = updh[t2] + sB2[t2] + (hpart[t2] + hpart[t2 + 64]);
        snew[t2] = v;
        g_slots[b * 512 + s * 64 + t2] = v;
        if (last) out[b * 512 + s * 64 + t2] = v;
    }
    WAITG(0);
    __syncthreads();

    if (!last)
        prep_slot(b, s, t2, snew, lns, qv, qtv, hpart, sLnsg, sLnsb,
                  (const float*)sWq, (const float*)sWk, sLng, sLnb);
}

// ---------------------------------------------------------------------------
extern "C" void kernel_launch(void* const* d_in, const int* in_sizes, int n_in,
                              void* d_out, int out_size)
{
    const float* x     = (const float*)d_in[0];
    const float* noise = (const float*)d_in[1];
    const float* mu    = (const float*)d_in[2];
    const float* lsig  = (const float*)d_in[3];
    const float* lng   = (const float*)d_in[4];
    const float* lnb   = (const float*)d_in[5];
    const float* lnsg  = (const float*)d_in[6];
    const float* lnsb  = (const float*)d_in[7];
    const float* lnmg  = (const float*)d_in[8];
    const float* lnmb  = (const float*)d_in[9];
    const float* Wq    = (const float*)d_in[10];
    const float* Wk    = (const float*)d_in[11];
    const float* Wv    = (const float*)d_in[12];
    const float* W_ih  = (const float*)d_in[13];
    const float* W_hh  = (const float*)d_in[14];
    const float* b_ih  = (const float*)d_in[15];
    const float* b_hh  = (const float*)d_in[16];
    const float* W1    = (const float*)d_in[17];
    const float* b1    = (const float*)d_in[18];
    const float* W2    = (const float*)d_in[19];
    const float* b2    = (const float*)d_in[20];
    float* out = (float*)d_out;

    cudaFuncSetAttribute(k_pass, cudaFuncAttributeMaxDynamicSharedMemorySize, SMEM_BYTES);
    cudaFuncSetAttribute(k_update, cudaFuncAttributeMaxDynamicSharedMemorySize, UPD_SMEM);
    cudaFuncSetAttribute(k_init, cudaFuncAttributeMaxDynamicSharedMemorySize, INIT_SMEM);

    k_init<<<BB * SS, 128, INIT_SMEM>>>(noise, mu, lsig, lnsg, lnsb, Wq, Wk, lng, lnb);

    cudaLaunchAttribute pdl[1];
    pdl[0].id = cudaLaunchAttributeProgrammaticStreamSerialization;
    pdl[0].val.programmaticStreamSerializationAllowed = 1;

    for (int it = 0; it < 3; ++it) {
        {
            cudaLaunchConfig_t cfg = {};
            cfg.gridDim = dim3(NBLKX, BB);
            cfg.blockDim = dim3(PASS_THREADS);
            cfg.dynamicSmemBytes = SMEM_BYTES;
            cfg.stream = 0;
            cfg.attrs = pdl;
            cfg.numAttrs = 1;
            cudaLaunchKernelEx(&cfg, k_pass, (const float4*)x);
        }
        {
            cudaLaunchConfig_t cfg = {};
            cfg.gridDim = dim3(128);
            cfg.blockDim = dim3(256);
            cfg.dynamicSmemBytes = UPD_SMEM;
            cfg.stream = 0;
            cfg.attrs = pdl;
            cfg.numAttrs = 1;
            cudaLaunchKernelEx(&cfg, k_update, lng, lnb, lnsg, lnsb, lnmg, lnmb,
                               Wq, Wk, Wv, W_ih, W_hh, b_ih, b_hh,
                               W1, b1, W2, b2, out, it == 2);
        }
    }
}